// round 2
// baseline (speedup 1.0000x reference)
#include <cuda_runtime.h>
#include <cuda_bf16.h>
#include <cstddef>

#define NN   50000
#define EE   800000
#define INC  128
#define OUTC 256
#define HALF 128
#define NR   6

// ---------------- scratch (module-scope device memory; no allocations) ------
__device__ float d_h1 [(size_t)NN * OUTC];
__device__ float d_h2 [(size_t)NN * OUTC];
__device__ float d_g1 [(size_t)NN * OUTC];
__device__ float d_g2 [(size_t)NN * OUTC];
__device__ float d_acc[(size_t)NN * NR * OUTC];   // per-node per-relation sums
__device__ int   d_cnt[NN * NR];
__device__ float d_inv[NN * NR];
__device__ float d_wc1[(size_t)(NR + 1) * INC  * OUTC];   // [root1; W1]  896 x 256
__device__ float d_wc2[(size_t)(NR + 1) * OUTC * OUTC];   // [root2; W2] 1792 x 256
__device__ float d_wc3[(size_t)(NR + 1) * OUTC * HALF];   // [root3; W3] 1792 x 128

// ---------------- edge-count / normalization --------------------------------
__global__ void count_k(const int* __restrict__ dst, const int* __restrict__ et,
                        int E, int* __restrict__ cnt)
{
    int e = blockIdx.x * blockDim.x + threadIdx.x;
    if (e < E) atomicAdd(&cnt[dst[e] * NR + et[e]], 1);
}

__global__ void inv_k(const int* __restrict__ cnt, float* __restrict__ inv, int n)
{
    int i = blockIdx.x * blockDim.x + threadIdx.x;
    if (i < n) {
        int c = cnt[i];
        inv[i] = 1.0f / (float)(c > 1 ? c : 1);
    }
}

// acc layout: [N][NR][d]; multiply each (node, rel) row by inv[node*NR+rel]
__global__ void norm_k(float* __restrict__ acc, const float* __restrict__ inv,
                       int N, int d)
{
    int d4   = d >> 2;
    int row4 = NR * d4;
    long long idx   = blockIdx.x * (long long)blockDim.x + threadIdx.x;
    long long total = (long long)N * row4;
    if (idx >= total) return;
    int i = (int)(idx / row4);
    int r = ((int)(idx % row4)) / d4;
    float s = inv[i * NR + r];
    float4* p = (float4*)acc + idx;
    float4 v = *p;
    v.x *= s; v.y *= s; v.z *= s; v.w *= s;
    *p = v;
}

// ---------------- edge scatter (sum of source features per (dst, rel)) ------
// one warp per edge; float4 atomicAdd (sm_90+ vector RED)
__global__ void scatter_k(const float* __restrict__ xf, int d,
                          const int* __restrict__ src, const int* __restrict__ dst,
                          const int* __restrict__ et, int E,
                          float* __restrict__ acc, int accld)
{
    int w    = (int)(((size_t)blockIdx.x * blockDim.x + threadIdx.x) >> 5);
    int lane = threadIdx.x & 31;
    if (w >= E) return;
    int s = src[w], t = dst[w], r = et[w];
    const float4* xs = (const float4*)(xf + (size_t)s * d);
    float4*       a  = (float4*)(acc + (size_t)t * accld + r * d);
    int n4 = d >> 2;
    for (int i = lane; i < n4; i += 32)
        atomicAdd(&a[i], xs[i]);
}

// ---------------- fp32 SGEMM: C = [A0 | A1] * B + bias (optional relu) ------
// A is a logical [M x K] row-major matrix: columns [0,d0) come from A0 (ld0),
// columns [d0,K) from A1 (ld1). K % 16 == 0, d0 % 16 == 0, Bld % 128 == 0.
// 128x128 block tile, 256 threads, 8x8 per thread, BK=16.
__global__ void __launch_bounds__(256)
gemm_k(const float* __restrict__ A0, const float* __restrict__ A1,
       int d0, int ld0, int ld1,
       const float* __restrict__ B, const float* __restrict__ bias,
       float* __restrict__ C, int ldc,
       int M, int K, int Bld, int relu)
{
    __shared__ float As[16][132];
    __shared__ float Bs[16][128];
    const int tid  = threadIdx.x;
    const int row0 = blockIdx.y * 128;
    const int col0 = blockIdx.x * 128;
    const int tx = tid & 15, ty = tid >> 4;

    float acc[8][8];
#pragma unroll
    for (int i = 0; i < 8; i++)
#pragma unroll
        for (int j = 0; j < 8; j++) acc[i][j] = 0.f;

    for (int k0 = 0; k0 < K; k0 += 16) {
        const float* Ab; int ld, kk;
        if (k0 < d0) { Ab = A0; ld = ld0; kk = k0; }
        else         { Ab = A1; ld = ld1; kk = k0 - d0; }
#pragma unroll
        for (int j = 0; j < 2; j++) {
            int idx = tid + j * 256;          // 512 float4 loads of the A tile
            int ar  = idx >> 2, kq = idx & 3;
            int gr  = row0 + ar;
            float4 v = make_float4(0.f, 0.f, 0.f, 0.f);
            if (gr < M) v = *(const float4*)(Ab + (size_t)gr * ld + kk + kq * 4);
            As[kq * 4 + 0][ar] = v.x;
            As[kq * 4 + 1][ar] = v.y;
            As[kq * 4 + 2][ar] = v.z;
            As[kq * 4 + 3][ar] = v.w;
        }
#pragma unroll
        for (int j = 0; j < 2; j++) {
            int idx = tid + j * 256;          // 512 float4 loads of the B tile
            int bk  = idx >> 5, bn = (idx & 31) * 4;
            *(float4*)&Bs[bk][bn] =
                *(const float4*)(B + (size_t)(k0 + bk) * Bld + col0 + bn);
        }
        __syncthreads();
#pragma unroll
        for (int k = 0; k < 16; k++) {
            float ra[8], rb[8];
            *(float4*)&ra[0] = *(const float4*)&As[k][ty * 8];
            *(float4*)&ra[4] = *(const float4*)&As[k][ty * 8 + 4];
            *(float4*)&rb[0] = *(const float4*)&Bs[k][tx * 8];
            *(float4*)&rb[4] = *(const float4*)&Bs[k][tx * 8 + 4];
#pragma unroll
            for (int i = 0; i < 8; i++)
#pragma unroll
                for (int j = 0; j < 8; j++)
                    acc[i][j] += ra[i] * rb[j];
        }
        __syncthreads();
    }

#pragma unroll
    for (int i = 0; i < 8; i++) {
        int gr = row0 + ty * 8 + i;
        if (gr < M) {
#pragma unroll
            for (int j = 0; j < 8; j += 4) {
                int gc = col0 + tx * 8 + j;
                float4 v;
                v.x = acc[i][j + 0] + bias[gc + 0];
                v.y = acc[i][j + 1] + bias[gc + 1];
                v.z = acc[i][j + 2] + bias[gc + 2];
                v.w = acc[i][j + 3] + bias[gc + 3];
                if (relu) {
                    v.x = fmaxf(v.x, 0.f); v.y = fmaxf(v.y, 0.f);
                    v.z = fmaxf(v.z, 0.f); v.w = fmaxf(v.w, 0.f);
                }
                *(float4*)(C + (size_t)gr * ldc + gc) = v;
            }
        }
    }
}

// ---------------- launch ------------------------------------------------------
extern "C" void kernel_launch(void* const* d_in, const int* in_sizes, int n_in,
                              void* d_out, int out_size)
{
    const float* x       = (const float*)d_in[0];
    const int*   eidx    = (const int*)  d_in[1];
    const int*   etype   = (const int*)  d_in[2];
    const float* enc_w0  = (const float*)d_in[3];
    const float* enc_b0  = (const float*)d_in[4];
    const float* enc_w1  = (const float*)d_in[5];
    const float* enc_b1  = (const float*)d_in[6];
    const float* enc_w2  = (const float*)d_in[7];
    const float* enc_b2  = (const float*)d_in[8];
    const float* W1      = (const float*)d_in[9];
    const float* root1   = (const float*)d_in[10];
    const float* b1      = (const float*)d_in[11];
    const float* W2      = (const float*)d_in[12];
    const float* root2   = (const float*)d_in[13];
    const float* b2      = (const float*)d_in[14];
    const float* W3      = (const float*)d_in[15];
    const float* root3   = (const float*)d_in[16];
    const float* b3      = (const float*)d_in[17];
    float* out = (float*)d_out;

    const int N = NN, E = EE;
    const int* src = eidx;
    const int* dst = eidx + E;

    float *h1, *h2, *g1, *g2, *acc, *inv, *wc1, *wc2, *wc3;
    int* cnt;
    cudaGetSymbolAddress((void**)&h1,  d_h1);
    cudaGetSymbolAddress((void**)&h2,  d_h2);
    cudaGetSymbolAddress((void**)&g1,  d_g1);
    cudaGetSymbolAddress((void**)&g2,  d_g2);
    cudaGetSymbolAddress((void**)&acc, d_acc);
    cudaGetSymbolAddress((void**)&cnt, d_cnt);
    cudaGetSymbolAddress((void**)&inv, d_inv);
    cudaGetSymbolAddress((void**)&wc1, d_wc1);
    cudaGetSymbolAddress((void**)&wc2, d_wc2);
    cudaGetSymbolAddress((void**)&wc3, d_wc3);

    // edge degree counts (shared by all three conv layers)
    cudaMemsetAsync(cnt, 0, (size_t)NR * N * sizeof(int));
    count_k<<<(E + 255) / 256, 256>>>(dst, etype, E, cnt);
    inv_k<<<(NR * N + 255) / 256, 256>>>(cnt, inv, NR * N);

    // stacked weights [root; W_0..W_5] (pure concatenation -> D2D copies)
    cudaMemcpyAsync(wc1,              root1, (size_t)INC  * OUTC * 4,      cudaMemcpyDeviceToDevice);
    cudaMemcpyAsync(wc1 + INC * OUTC, W1,    (size_t)NR * INC  * OUTC * 4, cudaMemcpyDeviceToDevice);
    cudaMemcpyAsync(wc2,               root2, (size_t)OUTC * OUTC * 4,      cudaMemcpyDeviceToDevice);
    cudaMemcpyAsync(wc2 + OUTC * OUTC, W2,    (size_t)NR * OUTC * OUTC * 4, cudaMemcpyDeviceToDevice);
    cudaMemcpyAsync(wc3,               root3, (size_t)OUTC * HALF * 4,      cudaMemcpyDeviceToDevice);
    cudaMemcpyAsync(wc3 + OUTC * HALF, W3,    (size_t)NR * OUTC * HALF * 4, cudaMemcpyDeviceToDevice);

    const dim3 blk(256);
    const int rowTiles = (N + 127) / 128;
    const int scatBlocks = (int)(((size_t)E * 32 + 255) / 256);

    // --- dense encoder branch: out[:, 0:128] ---
    gemm_k<<<dim3(2, rowTiles), blk>>>(x,  nullptr, INC,  INC,  0, enc_w0, enc_b0, h1,  OUTC, N, INC,  OUTC, 1);
    gemm_k<<<dim3(2, rowTiles), blk>>>(h1, nullptr, OUTC, OUTC, 0, enc_w1, enc_b1, h2,  OUTC, N, OUTC, OUTC, 1);
    gemm_k<<<dim3(1, rowTiles), blk>>>(h2, nullptr, OUTC, OUTC, 0, enc_w2, enc_b2, out, OUTC, N, OUTC, HALF, 0);

    // --- conv1: g1 = relu([x | mean_r(x)] @ [root1; W1] + b1), K = 896 ---
    cudaMemsetAsync(acc, 0, (size_t)N * NR * INC * 4);
    scatter_k<<<scatBlocks, blk>>>(x, INC, src, dst, etype, E, acc, NR * INC);
    {
        long long tot = (long long)N * NR * (INC / 4);
        norm_k<<<(unsigned)((tot + 255) / 256), blk>>>(acc, inv, N, INC);
    }
    gemm_k<<<dim3(2, rowTiles), blk>>>(x, acc, INC, INC, NR * INC, wc1, b1, g1, OUTC, N, (NR + 1) * INC, OUTC, 1);

    // --- conv2: g2 = relu([g1 | mean_r(g1)] @ [root2; W2] + b2), K = 1792 ---
    cudaMemsetAsync(acc, 0, (size_t)N * NR * OUTC * 4);
    scatter_k<<<scatBlocks, blk>>>(g1, OUTC, src, dst, etype, E, acc, NR * OUTC);
    {
        long long tot = (long long)N * NR * (OUTC / 4);
        norm_k<<<(unsigned)((tot + 255) / 256), blk>>>(acc, inv, N, OUTC);
    }
    gemm_k<<<dim3(2, rowTiles), blk>>>(g1, acc, OUTC, OUTC, NR * OUTC, wc2, b2, g2, OUTC, N, (NR + 1) * OUTC, OUTC, 1);

    // --- conv3: out[:, 128:256] = [g2 | mean_r(g2)] @ [root3; W3] + b3 ---
    cudaMemsetAsync(acc, 0, (size_t)N * NR * OUTC * 4);
    scatter_k<<<scatBlocks, blk>>>(g2, OUTC, src, dst, etype, E, acc, NR * OUTC);
    {
        long long tot = (long long)N * NR * (OUTC / 4);
        norm_k<<<(unsigned)((tot + 255) / 256), blk>>>(acc, inv, N, OUTC);
    }
    gemm_k<<<dim3(1, rowTiles), blk>>>(g2, acc, OUTC, OUTC, NR * OUTC, wc3, b3, out + HALF, OUTC, N, (NR + 1) * OUTC, HALF, 0);
}